// round 4
// baseline (speedup 1.0000x reference)
#include <cuda_runtime.h>
#include <cstdint>

#define NN     100000
#define EE     1000000
#define DIN    128
#define DOUT   64
#define DEDGE  11
#define ET     (EE + NN)

// ---------------- scratch (device globals) ----------------------------------
__device__ float g_xl[NN * DOUT];          // x @ W_l   (25.6 MB)
__device__ float g_xr[NN * DOUT];          // x @ W_r   (25.6 MB)
__device__ float g_deg[NN];
__device__ float g_loop_attr[NN * DEDGE];
__device__ float g_denom[NN];

// ---------------- 0: init ---------------------------------------------------
__global__ void k_init(float* __restrict__ out) {
    int i = blockIdx.x * blockDim.x + threadIdx.x;
    if (i < NN) {
        g_deg[i]   = 0.0f;
        g_denom[i] = 0.0f;
    }
    if (i < NN * DEDGE) g_loop_attr[i] = 0.0f;
    if (i < NN * DOUT)  out[i] = 0.0f;
}

// ---------------- 1: degree + incoming-attr sums ----------------------------
__global__ void k_deg(const int* __restrict__ ei, const float* __restrict__ ea) {
    int e = blockIdx.x * blockDim.x + threadIdx.x;
    if (e >= EE) return;
    int dst = __ldg(&ei[EE + e]);
    atomicAdd(&g_deg[dst], 1.0f);
    const float* a = ea + (size_t)e * DEDGE;
    float* la = g_loop_attr + (size_t)dst * DEDGE;
#pragma unroll
    for (int k = 0; k < DEDGE; k++) atomicAdd(&la[k], __ldg(&a[k]));
}

// ---------------- 2: normalize loop attrs (mean) -----------------------------
__global__ void k_norm() {
    int i = blockIdx.x * blockDim.x + threadIdx.x;
    if (i >= NN) return;
    float inv = 1.0f / fmaxf(g_deg[i], 1.0f);
#pragma unroll
    for (int k = 0; k < DEDGE; k++) g_loop_attr[i * DEDGE + k] *= inv;
}

// ---------------- 3: fused dual GEMM: xl = x@Wl, xr = x@Wr -------------------
// 256 threads = 32 col-pairs x 8 row-groups; each thread: 2 cols x 4 rows,
// both matrices => 16 accumulators. W loads are float2 (conflict-free),
// x loads are warp-broadcast float4. 32 rows per tile.
// smem: Wl 32KB + Wr 32KB + x 16KB = 80KB dynamic.
__global__ void __launch_bounds__(256, 2)
k_gemm(const float* __restrict__ x, const float* __restrict__ Wl,
       const float* __restrict__ Wr) {
    extern __shared__ float sm[];
    float* sWl = sm;            // 128*64
    float* sWr = sm + 8192;     // 128*64
    float* sx  = sm + 16384;    // 32*128

    {
        const float4* s = (const float4*)Wl;
        float4* d = (float4*)sWl;
        for (int i = threadIdx.x; i < 2048; i += 256) d[i] = s[i];
        s = (const float4*)Wr; d = (float4*)sWr;
        for (int i = threadIdx.x; i < 2048; i += 256) d[i] = s[i];
    }

    int cp = threadIdx.x & 31;   // col pair: cols 2cp, 2cp+1
    int rg = threadIdx.x >> 5;   // 0..7 row group (4 rows each)
    const int ROWS = 32;
    int ntiles = NN / ROWS;      // 3125 exactly

    const float2* sWl2 = (const float2*)sWl;
    const float2* sWr2 = (const float2*)sWr;

    for (int tile = blockIdx.x; tile < ntiles; tile += gridDim.x) {
        int row0 = tile * ROWS;
        __syncthreads();
        {
            const float4* xg = (const float4*)(x + (size_t)row0 * DIN);
            float4* sx4 = (float4*)sx;
            for (int i = threadIdx.x; i < (ROWS * DIN) / 4; i += 256) sx4[i] = xg[i];
        }
        __syncthreads();

        float accl[4][2] = {};
        float accr[4][2] = {};
#pragma unroll 4
        for (int k = 0; k < DIN; k += 4) {
            float2 wl[4], wr[4];
#pragma unroll
            for (int kk = 0; kk < 4; kk++) {
                wl[kk] = sWl2[(k + kk) * 32 + cp];
                wr[kk] = sWr2[(k + kk) * 32 + cp];
            }
#pragma unroll
            for (int r = 0; r < 4; r++) {
                float4 xv = *(const float4*)&sx[(rg * 4 + r) * DIN + k];
                accl[r][0] = fmaf(xv.x, wl[0].x, fmaf(xv.y, wl[1].x, fmaf(xv.z, wl[2].x, fmaf(xv.w, wl[3].x, accl[r][0]))));
                accl[r][1] = fmaf(xv.x, wl[0].y, fmaf(xv.y, wl[1].y, fmaf(xv.z, wl[2].y, fmaf(xv.w, wl[3].y, accl[r][1]))));
                accr[r][0] = fmaf(xv.x, wr[0].x, fmaf(xv.y, wr[1].x, fmaf(xv.z, wr[2].x, fmaf(xv.w, wr[3].x, accr[r][0]))));
                accr[r][1] = fmaf(xv.x, wr[0].y, fmaf(xv.y, wr[1].y, fmaf(xv.z, wr[2].y, fmaf(xv.w, wr[3].y, accr[r][1]))));
            }
        }
#pragma unroll
        for (int r = 0; r < 4; r++) {
            int row = row0 + rg * 4 + r;
            float2* pl = (float2*)&g_xl[(size_t)row * DOUT + 2 * cp];
            float2* pr = (float2*)&g_xr[(size_t)row * DOUT + 2 * cp];
            *pl = make_float2(accl[r][0], accl[r][1]);
            *pr = make_float2(accr[r][0], accr[r][1]);
        }
    }
}

// ---------------- 4: FUSED edge pass: logit -> exp -> denom + scatter --------
// One warp per edge. No segment-max: logits are O(±10) by construction, so
// exp() is safe in fp32 and softmax is shift-invariant.
// Lanes 0-15 gather xl[src] float4 chunks; lanes 16-31 gather xr[dst];
// exchange via shfl_xor(16). Lanes 0-15 then own xl in regs for the scatter.
__global__ void __launch_bounds__(256)
k_edge(const int* __restrict__ ei, const float* __restrict__ ea,
       const float* __restrict__ We, const float* __restrict__ att,
       float* __restrict__ out) {
    __shared__ float sWe[DEDGE * DOUT];
    __shared__ float sAtt[DOUT];
    for (int i = threadIdx.x; i < DEDGE * DOUT; i += 256) sWe[i] = We[i];
    if (threadIdx.x < DOUT) sAtt[threadIdx.x] = att[threadIdx.x];
    __syncthreads();

    int widx = (int)((blockIdx.x * blockDim.x + threadIdx.x) >> 5);
    int lane = threadIdx.x & 31;
    if (widx >= ET) return;

    int src, dst;
    const float* a;
    if (widx < EE) {
        src = __ldg(&ei[widx]);
        dst = __ldg(&ei[EE + widx]);
        a = ea + (size_t)widx * DEDGE;
    } else {
        src = dst = widx - EE;
        a = g_loop_attr + (size_t)(widx - EE) * DEDGE;
    }

    float av = (lane < DEDGE) ? a[lane] : 0.0f;

    int half = lane >> 4;        // 0 -> xl[src], 1 -> xr[dst]
    int c    = lane & 15;        // float4 chunk index (dims 4c..4c+3)

    const float4* gp = half ? (const float4*)(g_xr + (size_t)dst * DOUT)
                            : (const float4*)(g_xl + (size_t)src * DOUT);
    float4 g = gp[c];

    float4 o;
    o.x = __shfl_xor_sync(0xFFFFFFFFu, g.x, 16);
    o.y = __shfl_xor_sync(0xFFFFFFFFu, g.y, 16);
    o.z = __shfl_xor_sync(0xFFFFFFFFu, g.z, 16);
    o.w = __shfl_xor_sync(0xFFFFFFFFu, g.w, 16);
    float4 xlv = half ? o : g;
    float4 xrv = half ? g : o;

    // e chunk for dims 4c..4c+3
    float4 e = make_float4(0.f, 0.f, 0.f, 0.f);
    const float4* sWe4 = (const float4*)sWe;
#pragma unroll
    for (int k = 0; k < DEDGE; k++) {
        float ak = __shfl_sync(0xFFFFFFFFu, av, k);
        float4 w = sWe4[k * 16 + c];
        e.x = fmaf(ak, w.x, e.x);
        e.y = fmaf(ak, w.y, e.y);
        e.z = fmaf(ak, w.z, e.z);
        e.w = fmaf(ak, w.w, e.w);
    }

    float m0 = xlv.x + xrv.x + e.x;  m0 = (m0 >= 0.f) ? m0 : 0.2f * m0;
    float m1 = xlv.y + xrv.y + e.y;  m1 = (m1 >= 0.f) ? m1 : 0.2f * m1;
    float m2 = xlv.z + xrv.z + e.z;  m2 = (m2 >= 0.f) ? m2 : 0.2f * m2;
    float m3 = xlv.w + xrv.w + e.w;  m3 = (m3 >= 0.f) ? m3 : 0.2f * m3;

    const float4* sAtt4 = (const float4*)sAtt;
    float4 at = sAtt4[c];
    float v = fmaf(m0, at.x, fmaf(m1, at.y, fmaf(m2, at.z, m3 * at.w)));
    // reduce over 16 lanes (each half computes identical result)
#pragma unroll
    for (int off = 8; off > 0; off >>= 1)
        v += __shfl_xor_sync(0xFFFFFFFFu, v, off);

    float ex = __expf(v);   // no max subtraction needed (|v| small)

    if (lane == 0) atomicAdd(&g_denom[dst], ex);

    if (lane < 16) {
        float4 w4;
        w4.x = ex * xlv.x; w4.y = ex * xlv.y; w4.z = ex * xlv.z; w4.w = ex * xlv.w;
        float* p = out + (size_t)dst * DOUT + c * 4;
        unsigned long long gpa = (unsigned long long)__cvta_generic_to_global(p);
        asm volatile("red.global.add.v4.f32 [%0], {%1,%2,%3,%4};"
                     :: "l"(gpa), "f"(w4.x), "f"(w4.y), "f"(w4.z), "f"(w4.w)
                     : "memory");
    }
}

// ---------------- 5: final divide by softmax denominator ---------------------
__global__ void k_final(float* __restrict__ out) {
    int i = blockIdx.x * blockDim.x + threadIdx.x;
    if (i >= NN * DOUT) return;
    out[i] = out[i] / g_denom[i >> 6];
}

// ---------------- launch -----------------------------------------------------
extern "C" void kernel_launch(void* const* d_in, const int* in_sizes, int n_in,
                              void* d_out, int out_size) {
    const float* x   = (const float*)d_in[0];
    const int*   ei  = (const int*)  d_in[1];
    const float* ea  = (const float*)d_in[2];
    const float* Wl  = (const float*)d_in[3];
    const float* Wr  = (const float*)d_in[4];
    const float* We  = (const float*)d_in[5];
    const float* att = (const float*)d_in[6];
    float* out = (float*)d_out;

    cudaFuncSetAttribute(k_gemm, cudaFuncAttributeMaxDynamicSharedMemorySize, 81920);

    k_init <<<(NN * DOUT + 255) / 256, 256>>>(out);
    k_deg  <<<(EE + 255) / 256, 256>>>(ei, ea);
    k_norm <<<(NN + 255) / 256, 256>>>();
    k_gemm <<<296, 256, 81920>>>(x, Wl, Wr);
    k_edge <<<(ET * 32 + 255) / 256, 256>>>(ei, ea, We, att, out);
    k_final<<<(NN * DOUT + 255) / 256, 256>>>(out);
}

// round 5
// speedup vs baseline: 1.7172x; 1.7172x over previous
#include <cuda_runtime.h>
#include <cstdint>

#define NN     100000
#define EE     1000000
#define DIN    128
#define DOUT   64
#define DEDGE  11
#define ET     (EE + NN)

// ---------------- scratch (device globals) ----------------------------------
__device__ float g_xl[NN * DOUT];          // x @ W_l   (25.6 MB)
__device__ float g_xr[NN * DOUT];          // x @ W_r   (25.6 MB)
__device__ float g_ex[ET];                 // per-edge exp(logit) (4.4 MB)
__device__ float4 g_la4[NN * 3];           // padded loop-attr rows: 12 floats
                                           // slots 0..10 = attr sums, 11 = deg
__device__ float g_denom[NN];

// ---------------- 0: init ---------------------------------------------------
__global__ void k_init(float* __restrict__ out) {
    int i = blockIdx.x * blockDim.x + threadIdx.x;
    if (i < NN) g_denom[i] = 0.0f;
    if (i < NN * 3) g_la4[i] = make_float4(0.f, 0.f, 0.f, 0.f);
    if (i < NN * DOUT) out[i] = 0.0f;
}

// ---------------- 1: degree + incoming-attr sums (3x v4 red per edge) --------
__global__ void k_deg(const int* __restrict__ ei, const float* __restrict__ ea) {
    int e = blockIdx.x * blockDim.x + threadIdx.x;
    if (e >= EE) return;
    int dst = __ldg(&ei[EE + e]);
    const float* a = ea + (size_t)e * DEDGE;
    float v[12];
#pragma unroll
    for (int k = 0; k < DEDGE; k++) v[k] = __ldg(&a[k]);
    v[11] = 1.0f;  // degree count packed in slot 11
    float* base = (float*)(g_la4 + (size_t)dst * 3);
#pragma unroll
    for (int q = 0; q < 3; q++) {
        unsigned long long gp =
            (unsigned long long)__cvta_generic_to_global(base + 4 * q);
        asm volatile("red.global.add.v4.f32 [%0], {%1,%2,%3,%4};"
                     :: "l"(gp), "f"(v[4*q]), "f"(v[4*q+1]),
                        "f"(v[4*q+2]), "f"(v[4*q+3])
                     : "memory");
    }
}

// ---------------- 2: normalize loop attrs (mean) -----------------------------
__global__ void k_norm() {
    int i = blockIdx.x * blockDim.x + threadIdx.x;
    if (i >= NN) return;
    float* row = (float*)(g_la4 + (size_t)i * 3);
    float inv = 1.0f / fmaxf(row[11], 1.0f);
#pragma unroll
    for (int k = 0; k < DEDGE; k++) row[k] *= inv;
}

// ---------------- 3: fused dual GEMM (R3 version, known 120us) ---------------
__global__ void __launch_bounds__(256, 2)
k_gemm(const float* __restrict__ x, const float* __restrict__ Wl,
       const float* __restrict__ Wr) {
    extern __shared__ float sm[];
    float* sWl = sm;            // 128*64
    float* sWr = sm + 8192;     // 128*64
    float* sx  = sm + 16384;    // 16*128

    {
        const float4* s = (const float4*)Wl;
        float4* d = (float4*)sWl;
        for (int i = threadIdx.x; i < 2048; i += 256) d[i] = s[i];
        s = (const float4*)Wr; d = (float4*)sWr;
        for (int i = threadIdx.x; i < 2048; i += 256) d[i] = s[i];
    }

    int dcol = threadIdx.x & 63;
    int rg   = threadIdx.x >> 6;  // 0..3
    const int ROWS = 16;
    int ntiles = NN / ROWS;       // 6250 exactly

    for (int tile = blockIdx.x; tile < ntiles; tile += gridDim.x) {
        int row0 = tile * ROWS;
        __syncthreads();
        {
            const float4* xg = (const float4*)(x + (size_t)row0 * DIN);
            float4* sx4 = (float4*)sx;
            for (int i = threadIdx.x; i < (ROWS * DIN) / 4; i += 256) sx4[i] = xg[i];
        }
        __syncthreads();

        float accl[4] = {0, 0, 0, 0};
        float accr[4] = {0, 0, 0, 0};
#pragma unroll 8
        for (int k = 0; k < DIN; k += 4) {
            float wl0 = sWl[(k + 0) * 64 + dcol];
            float wl1 = sWl[(k + 1) * 64 + dcol];
            float wl2 = sWl[(k + 2) * 64 + dcol];
            float wl3 = sWl[(k + 3) * 64 + dcol];
            float wr0 = sWr[(k + 0) * 64 + dcol];
            float wr1 = sWr[(k + 1) * 64 + dcol];
            float wr2 = sWr[(k + 2) * 64 + dcol];
            float wr3 = sWr[(k + 3) * 64 + dcol];
#pragma unroll
            for (int r = 0; r < 4; r++) {
                float4 xv = *(const float4*)&sx[(rg * 4 + r) * DIN + k];
                accl[r] = fmaf(xv.x, wl0, fmaf(xv.y, wl1, fmaf(xv.z, wl2, fmaf(xv.w, wl3, accl[r]))));
                accr[r] = fmaf(xv.x, wr0, fmaf(xv.y, wr1, fmaf(xv.z, wr2, fmaf(xv.w, wr3, accr[r]))));
            }
        }
#pragma unroll
        for (int r = 0; r < 4; r++) {
            int row = row0 + rg * 4 + r;
            g_xl[row * DOUT + dcol] = accl[r];
            g_xr[row * DOUT + dcol] = accr[r];
        }
    }
}

// ---------------- 4: per-edge logit -> exp -> denom --------------------------
// One warp per edge (R3 layout). No segment-max (validated safe in fp32).
__global__ void __launch_bounds__(256)
k_logits(const int* __restrict__ ei, const float* __restrict__ ea,
         const float* __restrict__ We, const float* __restrict__ att) {
    __shared__ float sWe[DEDGE * DOUT];   // row-major, read as float2
    __shared__ float sAtt[DOUT];
    for (int i = threadIdx.x; i < DEDGE * DOUT; i += 256) sWe[i] = We[i];
    if (threadIdx.x < DOUT) sAtt[threadIdx.x] = att[threadIdx.x];
    __syncthreads();

    int widx = (int)((blockIdx.x * blockDim.x + threadIdx.x) >> 5);
    int lane = threadIdx.x & 31;
    if (widx >= ET) return;

    int src, dst;
    const float* a;
    if (widx < EE) {
        src = __ldg(&ei[widx]);
        dst = __ldg(&ei[EE + widx]);
        a = ea + (size_t)widx * DEDGE;
    } else {
        src = dst = widx - EE;
        a = (const float*)(g_la4 + (size_t)(widx - EE) * 3);
    }

    float av = (lane < DEDGE) ? a[lane] : 0.0f;

    const float2* sWe2 = (const float2*)sWe;
    float e0 = 0.0f, e1 = 0.0f;
#pragma unroll
    for (int k = 0; k < DEDGE; k++) {
        float ak = __shfl_sync(0xFFFFFFFFu, av, k);
        float2 w = sWe2[k * 32 + lane];
        e0 = fmaf(ak, w.x, e0);
        e1 = fmaf(ak, w.y, e1);
    }

    float2 xlv = ((const float2*)g_xl)[(size_t)src * 32 + lane];
    float2 xrv = ((const float2*)g_xr)[(size_t)dst * 32 + lane];
    float m0 = xlv.x + xrv.x + e0;  m0 = (m0 >= 0.0f) ? m0 : 0.2f * m0;
    float m1 = xlv.y + xrv.y + e1;  m1 = (m1 >= 0.0f) ? m1 : 0.2f * m1;

    const float2* sAtt2 = (const float2*)sAtt;
    float2 at = sAtt2[lane];
    float v = m0 * at.x + m1 * at.y;
#pragma unroll
    for (int o = 16; o > 0; o >>= 1) v += __shfl_xor_sync(0xFFFFFFFFu, v, o);

    if (lane == 0) {
        float ex = __expf(v);            // no max subtraction needed
        g_ex[widx] = ex;
        atomicAdd(&g_denom[dst], ex);
    }
}

// ---------------- 5: weighted scatter (half-warp per edge) -------------------
__global__ void __launch_bounds__(256)
k_accum(const int* __restrict__ ei, float* __restrict__ out) {
    int h = (int)((blockIdx.x * blockDim.x + threadIdx.x) >> 4);  // edge idx
    int c = threadIdx.x & 15;                                      // chunk 0..15
    if (h >= ET) return;

    int src, dst;
    if (h < EE) {
        src = __ldg(&ei[h]);
        dst = __ldg(&ei[EE + h]);
    } else {
        src = dst = h - EE;
    }

    float ex = __ldg(&g_ex[h]);
    float4 xlv = ((const float4*)g_xl)[(size_t)src * 16 + c];
    float4 w;
    w.x = ex * xlv.x; w.y = ex * xlv.y; w.z = ex * xlv.z; w.w = ex * xlv.w;
    float* p = out + (size_t)dst * DOUT + c * 4;
    unsigned long long gp = (unsigned long long)__cvta_generic_to_global(p);
    asm volatile("red.global.add.v4.f32 [%0], {%1,%2,%3,%4};"
                 :: "l"(gp), "f"(w.x), "f"(w.y), "f"(w.z), "f"(w.w)
                 : "memory");
}

// ---------------- 6: final divide by softmax denominator ---------------------
__global__ void k_final(float* __restrict__ out) {
    int i = blockIdx.x * blockDim.x + threadIdx.x;
    if (i >= NN * DOUT) return;
    out[i] = out[i] / g_denom[i >> 6];
}

// ---------------- launch -----------------------------------------------------
extern "C" void kernel_launch(void* const* d_in, const int* in_sizes, int n_in,
                              void* d_out, int out_size) {
    const float* x   = (const float*)d_in[0];
    const int*   ei  = (const int*)  d_in[1];
    const float* ea  = (const float*)d_in[2];
    const float* Wl  = (const float*)d_in[3];
    const float* Wr  = (const float*)d_in[4];
    const float* We  = (const float*)d_in[5];
    const float* att = (const float*)d_in[6];
    float* out = (float*)d_out;

    cudaFuncSetAttribute(k_gemm, cudaFuncAttributeMaxDynamicSharedMemorySize, 73728);

    k_init  <<<(NN * DOUT + 255) / 256, 256>>>(out);
    k_deg   <<<(EE + 255) / 256, 256>>>(ei, ea);
    k_norm  <<<(NN + 255) / 256, 256>>>();
    k_gemm  <<<296, 256, 73728>>>(x, Wl, Wr);
    k_logits<<<(ET * 32 + 255) / 256, 256>>>(ei, ea, We, att);
    k_accum <<<(ET * 16 + 255) / 256, 256>>>(ei, out);
    k_final <<<(NN * DOUT + 255) / 256, 256>>>(out);
}